// round 2
// baseline (speedup 1.0000x reference)
#include <cuda_runtime.h>
#include <math.h>

#define TT 2048
#define BB 64
#define DD 256
#define HH 512

#define NGROUPS 8     // groups of batch elements
#define GC 16         // CTAs per group
#define GB 8          // batch elems per group
#define JC 32         // output columns owned per CTA
#define NT 256        // threads per CTA (phase 2)

// ---------------- device scratch (allocation-free rule: __device__ globals) ---------
__device__ float g_Gx[(size_t)TT * 3 * BB * HH];   // precomputed x-projections + bias
__device__ float g_h[BB * HH];                     // current hidden state
__device__ float g_rh[BB * HH];                    // r * h exchange buffer
__device__ unsigned g_bcnt[NGROUPS];               // barrier arrive counters
__device__ unsigned g_bgen[NGROUPS];               // barrier generations (monotonic)

// ---------------- group barrier (sense-reversing, generation-based) -----------------
__device__ __forceinline__ void group_barrier(int grp) {
    __syncthreads();
    if (threadIdx.x == 0) {
        volatile unsigned* vgen = (volatile unsigned*)&g_bgen[grp];
        unsigned gen = *vgen;
        __threadfence();                       // make this CTA's prior stores visible
        unsigned old = atomicAdd(&g_bcnt[grp], 1u);
        if (old == GC - 1u) {
            atomicExch(&g_bcnt[grp], 0u);      // reset counter for next use
            __threadfence();
            *vgen = gen + 1u;                  // release
        } else {
            while (*vgen == gen) { }           // spin on L2
            __threadfence();                   // acquire
        }
    }
    __syncthreads();
}

// =====================================================================================
// Phase 1: Gx[t][g][b][j] = x[t,b,:] @ Wg[0:256, j] + bg[j]   (parallel GEMM)
// M = T*B = 131072, K = 256, N = 512 per gate (3 gates), fp32 SIMT tiled.
// =====================================================================================
__global__ void __launch_bounds__(256) phase1_gemm(
    const float* __restrict__ x,
    const float* __restrict__ Wz, const float* __restrict__ bz,
    const float* __restrict__ Wr, const float* __restrict__ br,
    const float* __restrict__ Wh, const float* __restrict__ bh)
{
    __shared__ float xs[64 * 128];   // [k][m]  (k-chunk of 64, 128 rows)
    __shared__ float ws[64 * 64];    // [k][n]

    const int gate = blockIdx.y >> 3;                 // 0=z,1=r,2=h
    const int jt0  = (blockIdx.y & 7) * 64;           // n-tile origin
    const float* W    = (gate == 0) ? Wz : ((gate == 1) ? Wr : Wh);
    const float* bias = (gate == 0) ? bz : ((gate == 1) ? br : bh);
    const int m0  = blockIdx.x * 128;
    const int tid = threadIdx.x;
    const int tm = tid & 15;          // 16 m-tiles of 8 rows
    const int tn = tid >> 4;          // 16 n-tiles of 4 cols

    float acc[8][4];
#pragma unroll
    for (int i = 0; i < 8; i++)
#pragma unroll
        for (int j = 0; j < 4; j++) acc[i][j] = 0.f;

    for (int kc = 0; kc < 4; kc++) {
        // load x chunk [128 m][64 k] transposed -> xs[k][m]
#pragma unroll
        for (int i = 0; i < 32; i++) {
            int idx = tid + i * 256;
            int row = idx >> 6, kk = idx & 63;
            xs[kk * 128 + row] = x[(size_t)(m0 + row) * DD + kc * 64 + kk];
        }
        // load W chunk [64 k][64 n]
#pragma unroll
        for (int i = 0; i < 16; i++) {
            int idx = tid + i * 256;
            int kk = idx >> 6, jj = idx & 63;
            ws[kk * 64 + jj] = W[(size_t)(kc * 64 + kk) * HH + jt0 + jj];
        }
        __syncthreads();
#pragma unroll 8
        for (int kk = 0; kk < 64; kk++) {
            float4 w4 = *(const float4*)&ws[kk * 64 + tn * 4];
            float4 xA = *(const float4*)&xs[kk * 128 + tm * 8];
            float4 xB = *(const float4*)&xs[kk * 128 + tm * 8 + 4];
            float hv[8] = {xA.x, xA.y, xA.z, xA.w, xB.x, xB.y, xB.z, xB.w};
            float wv[4] = {w4.x, w4.y, w4.z, w4.w};
#pragma unroll
            for (int i = 0; i < 8; i++)
#pragma unroll
                for (int j = 0; j < 4; j++)
                    acc[i][j] = fmaf(hv[i], wv[j], acc[i][j]);
        }
        __syncthreads();
    }

    // epilogue: Gx layout [t][gate][b][j]
#pragma unroll
    for (int i = 0; i < 8; i++) {
        int m = m0 + tm * 8 + i;
        int t = m >> 6, b = m & 63;
        size_t base = (((size_t)t * 3 + gate) * BB + b) * HH + jt0 + tn * 4;
#pragma unroll
        for (int j = 0; j < 4; j++)
            g_Gx[base + j] = acc[i][j] + bias[jt0 + tn * 4 + j];
    }
}

// =====================================================================================
// Phase 2: persistent GRU recurrence.
// Grid = 128 CTAs = 8 groups x 16 CTAs. Group g owns batch rows [8g, 8g+8).
// CTA rank r owns columns [32r, 32r+32) for all 3 gates; recurrent weight slices
// (rows 256..767 of Wz/Wr/Wh) live in SMEM for the whole kernel.
// Per step: stage1 -> z (smem), r*h (global, .cg) -> barrier -> stage2 -> h_new.
// =====================================================================================
__global__ void __launch_bounds__(NT) phase2_gru(
    const float* __restrict__ h0,
    const float* __restrict__ Wz,
    const float* __restrict__ Wr,
    const float* __restrict__ Wh,
    float* __restrict__ out)
{
    extern __shared__ float sm[];
    float* wzs  = sm;                    // [512][32]
    float* wrs  = wzs + HH * JC;
    float* whs  = wrs + HH * JC;
    float* hbuf = whs + HH * JC;         // [512][8]  (k-major, b-minor); reused for rh
    float* z_s  = hbuf + HH * GB;        // [8][32]
    float* ho_s = z_s + GB * JC;         // [8][32]

    const int grp  = blockIdx.x >> 4;
    const int rank = blockIdx.x & 15;
    const int b0 = grp * GB;
    const int j0 = rank * JC;
    const int tid = threadIdx.x;

    // -------- load resident recurrent weight slices (rows DD..DD+511) --------
    for (int idx = tid; idx < HH * JC; idx += NT) {
        int k = idx >> 5, jl = idx & 31;
        size_t goff = (size_t)(DD + k) * HH + j0 + jl;
        wzs[idx] = Wz[goff];
        wrs[idx] = Wr[goff];
        whs[idx] = Wh[goff];
    }
    __syncthreads();

    // stage-1 work mapping: 16 tiles (2 gates x 8 j-tiles of 4 cols) x 16 k-chunks(32)
    const int tile1 = tid >> 4;          // 0..15
    const int kc1   = tid & 15;          // 0..15
    const int gate1 = tile1 >> 3;        // 0=z, 1=r
    const int jt1   = tile1 & 7;
    // stage-2 mapping: 8 j-tiles x 32 k-chunks(16)
    const int jt2 = tid >> 5;            // 0..7
    const int kc2 = tid & 31;            // 0..31

    for (int t = 0; t < TT; t++) {
        // ================= stage 1: z and r gates =================
        const float* hsrc = (t == 0) ? h0 : (const float*)g_h;
#pragma unroll
        for (int b = 0; b < GB; b++) {
#pragma unroll
            for (int q = 0; q < 2; q++) {
                int kk = tid + q * NT;   // 0..511
                hbuf[kk * GB + b] = __ldcg(&hsrc[(size_t)(b0 + b) * HH + kk]);
            }
        }
        __syncthreads();

        // stash h_old for own columns (read in stage-2 update, after hbuf is reused)
        {
            int b = tid >> 5, jl = tid & 31;
            ho_s[tid] = hbuf[(j0 + jl) * GB + b];
        }

        // prefetch Gx for this step (covers dot latency)
        float gx1[8][4];
        if (kc1 == 0) {
            size_t base = (((size_t)t * 3 + gate1) * BB + b0) * HH + j0 + jt1 * 4;
#pragma unroll
            for (int b = 0; b < 8; b++)
#pragma unroll
                for (int j = 0; j < 4; j++)
                    gx1[b][j] = __ldg(&g_Gx[base + (size_t)b * HH + j]);
        }
        float gx2[8][4];
        if (kc2 == 0) {
            size_t base = (((size_t)t * 3 + 2) * BB + b0) * HH + j0 + jt2 * 4;
#pragma unroll
            for (int b = 0; b < 8; b++)
#pragma unroll
                for (int j = 0; j < 4; j++)
                    gx2[b][j] = __ldg(&g_Gx[base + (size_t)b * HH + j]);
        }

        // dot1: acc[b][j] = sum_k h[b][k] * Wg_h[k][j]  over this thread's k-chunk(32)
        float acc[8][4];
#pragma unroll
        for (int i = 0; i < 8; i++)
#pragma unroll
            for (int j = 0; j < 4; j++) acc[i][j] = 0.f;
        {
            const float* wsel = (gate1 == 0) ? wzs : wrs;
            const float* wp = wsel + (kc1 * 32) * JC + jt1 * 4;
            const float* hp = hbuf + (kc1 * 32) * GB;
#pragma unroll 4
            for (int kk = 0; kk < 32; kk++) {
                float4 w4 = *(const float4*)(wp + kk * JC);
                float4 hA = *(const float4*)(hp + kk * GB);
                float4 hB = *(const float4*)(hp + kk * GB + 4);
                float hv[8] = {hA.x, hA.y, hA.z, hA.w, hB.x, hB.y, hB.z, hB.w};
                float wv[4] = {w4.x, w4.y, w4.z, w4.w};
#pragma unroll
                for (int i = 0; i < 8; i++)
#pragma unroll
                    for (int j = 0; j < 4; j++)
                        acc[i][j] = fmaf(hv[i], wv[j], acc[i][j]);
            }
        }
        // reduce partials across 16 k-chunks (16-lane butterfly)
#pragma unroll
        for (int i = 0; i < 8; i++)
#pragma unroll
            for (int j = 0; j < 4; j++) {
                float v = acc[i][j];
                v += __shfl_xor_sync(0xffffffffu, v, 8, 16);
                v += __shfl_xor_sync(0xffffffffu, v, 4, 16);
                v += __shfl_xor_sync(0xffffffffu, v, 2, 16);
                v += __shfl_xor_sync(0xffffffffu, v, 1, 16);
                acc[i][j] = v;
            }

        if (kc1 == 0) {
#pragma unroll
            for (int b = 0; b < 8; b++)
#pragma unroll
                for (int j = 0; j < 4; j++) {
                    int jl = jt1 * 4 + j;
                    float pre = acc[b][j] + gx1[b][j];
                    float s = 1.f / (1.f + __expf(-pre));
                    if (gate1 == 0) {
                        z_s[b * JC + jl] = s;
                    } else {
                        float rhv = s * hbuf[(j0 + jl) * GB + b];
                        __stcg(&g_rh[(size_t)(b0 + b) * HH + j0 + jl], rhv);
                    }
                }
        }

        group_barrier(grp);   // g_rh complete group-wide

        // ================= stage 2: candidate + update =================
#pragma unroll
        for (int b = 0; b < GB; b++) {
#pragma unroll
            for (int q = 0; q < 2; q++) {
                int kk = tid + q * NT;
                hbuf[kk * GB + b] = __ldcg(&g_rh[(size_t)(b0 + b) * HH + kk]);
            }
        }
        __syncthreads();

        float acc2[8][4];
#pragma unroll
        for (int i = 0; i < 8; i++)
#pragma unroll
            for (int j = 0; j < 4; j++) acc2[i][j] = 0.f;
        {
            const float* wp = whs + (kc2 * 16) * JC + jt2 * 4;
            const float* hp = hbuf + (kc2 * 16) * GB;
#pragma unroll 4
            for (int kk = 0; kk < 16; kk++) {
                float4 w4 = *(const float4*)(wp + kk * JC);
                float4 hA = *(const float4*)(hp + kk * GB);
                float4 hB = *(const float4*)(hp + kk * GB + 4);
                float hv[8] = {hA.x, hA.y, hA.z, hA.w, hB.x, hB.y, hB.z, hB.w};
                float wv[4] = {w4.x, w4.y, w4.z, w4.w};
#pragma unroll
                for (int i = 0; i < 8; i++)
#pragma unroll
                    for (int j = 0; j < 4; j++)
                        acc2[i][j] = fmaf(hv[i], wv[j], acc2[i][j]);
            }
        }
        // reduce across 32 k-chunks (full-warp butterfly)
#pragma unroll
        for (int i = 0; i < 8; i++)
#pragma unroll
            for (int j = 0; j < 4; j++) {
                float v = acc2[i][j];
                v += __shfl_xor_sync(0xffffffffu, v, 16, 32);
                v += __shfl_xor_sync(0xffffffffu, v, 8, 32);
                v += __shfl_xor_sync(0xffffffffu, v, 4, 32);
                v += __shfl_xor_sync(0xffffffffu, v, 2, 32);
                v += __shfl_xor_sync(0xffffffffu, v, 1, 32);
                acc2[i][j] = v;
            }

        if (kc2 == 0) {
#pragma unroll
            for (int b = 0; b < 8; b++)
#pragma unroll
                for (int j = 0; j < 4; j++) {
                    int jl = jt2 * 4 + j;
                    float ht = tanhf(acc2[b][j] + gx2[b][j]);
                    float z  = z_s[b * JC + jl];
                    float ho = ho_s[b * JC + jl];
                    float hn = ho + z * (ht - ho);
                    __stcg(&g_h[(size_t)(b0 + b) * HH + j0 + jl], hn);
                    out[((size_t)t * BB + b0 + b) * HH + j0 + jl] = hn;
                }
        }

        group_barrier(grp);   // g_h complete before next step reads it
    }
}

// =====================================================================================
extern "C" void kernel_launch(void* const* d_in, const int* in_sizes, int n_in,
                              void* d_out, int out_size)
{
    const float* x  = (const float*)d_in[0];
    const float* h0 = (const float*)d_in[1];
    const float* Wz = (const float*)d_in[2];
    const float* bz = (const float*)d_in[3];
    const float* Wr = (const float*)d_in[4];
    const float* br = (const float*)d_in[5];
    const float* Wh = (const float*)d_in[6];
    const float* bh = (const float*)d_in[7];
    float* out = (float*)d_out;

    const int smem_bytes = (3 * HH * JC + HH * GB + 2 * GB * JC) * (int)sizeof(float); // 215040
    cudaFuncSetAttribute(phase2_gru, cudaFuncAttributeMaxDynamicSharedMemorySize, smem_bytes);

    dim3 g1((TT * BB) / 128, 24);   // 1024 x 24 tiles of 128m x 64n
    phase1_gemm<<<g1, 256>>>(x, Wz, bz, Wr, br, Wh, bh);

    phase2_gru<<<NGROUPS * GC, NT, smem_bytes>>>(h0, Wz, Wr, Wh, out);
}

// round 3
// speedup vs baseline: 2.9676x; 2.9676x over previous
#include <cuda_runtime.h>
#include <math.h>

#define TT 2048
#define BB 64
#define DD 256
#define HH 512

#define NGROUPS 8     // groups of batch elements
#define GC 16         // CTAs per group
#define GB 8          // batch elems per group
#define JC 32         // output columns owned per CTA
#define NT 256        // threads per CTA (phase 2)
#define HPAD 12       // padded floats per hbuf row (8 used + 4 pad, 48B, 16B-aligned)

// ---------------- device scratch ----------------
__device__ float g_Gx[(size_t)TT * 3 * BB * HH];   // precomputed x-projections + bias
__device__ float g_h[BB * HH];                     // current hidden state
__device__ float g_rh[BB * HH];                    // r * h exchange buffer
__device__ unsigned g_bcnt[NGROUPS];               // barrier arrive counters
__device__ unsigned g_bgen[NGROUPS];               // barrier generations (monotonic)

// ---------------- group barrier (generation-based, graph-replay safe) ----------------
__device__ __forceinline__ void group_barrier(int grp) {
    __syncthreads();
    if (threadIdx.x == 0) {
        volatile unsigned* vgen = (volatile unsigned*)&g_bgen[grp];
        unsigned gen = *vgen;
        __threadfence();
        unsigned old = atomicAdd(&g_bcnt[grp], 1u);
        if (old == GC - 1u) {
            atomicExch(&g_bcnt[grp], 0u);
            __threadfence();
            *vgen = gen + 1u;
        } else {
            while (*vgen == gen) { }
            __threadfence();
        }
    }
    __syncthreads();
}

// =====================================================================================
// Phase 1: Gx[t][gate][b][j] = x[t,b,:] @ Wg[0:256, :] + bg     (parallel GEMM)
// Conflict-free: tn (cols) on low lane bits -> ws reads 16B-strided; xs reads broadcast.
// xs rows padded to 132 floats -> STS conflict-free, float4 loads stay 16B-aligned.
// =====================================================================================
__global__ void __launch_bounds__(256) phase1_gemm(
    const float* __restrict__ x,
    const float* __restrict__ Wz, const float* __restrict__ bz,
    const float* __restrict__ Wr, const float* __restrict__ br,
    const float* __restrict__ Wh, const float* __restrict__ bh)
{
    __shared__ float xs[32 * 132];   // [k][m] padded
    __shared__ float ws[32 * 64];    // [k][n]

    const int gate = blockIdx.y >> 3;
    const int jt0  = (blockIdx.y & 7) * 64;
    const float* W    = (gate == 0) ? Wz : ((gate == 1) ? Wr : Wh);
    const float* bias = (gate == 0) ? bz : ((gate == 1) ? br : bh);
    const int m0  = blockIdx.x * 128;
    const int tid = threadIdx.x;
    const int tn = tid & 15;          // 16 n-tiles of 4 cols (low bits -> conflict-free ws)
    const int tm = tid >> 4;          // 16 m-tiles of 8 rows (broadcast xs)

    float acc[8][4];
#pragma unroll
    for (int i = 0; i < 8; i++)
#pragma unroll
        for (int j = 0; j < 4; j++) acc[i][j] = 0.f;

    for (int kc = 0; kc < 8; kc++) {
        // x chunk [128 m][32 k] -> xs[k][m] (padded rows)
#pragma unroll
        for (int i = 0; i < 16; i++) {
            int idx = tid + i * 256;
            int row = idx >> 5, kk = idx & 31;
            xs[kk * 132 + row] = x[(size_t)(m0 + row) * DD + kc * 32 + kk];
        }
        // W chunk [32 k][64 n]
#pragma unroll
        for (int i = 0; i < 8; i++) {
            int idx = tid + i * 256;
            int kk = idx >> 6, jj = idx & 63;
            ws[kk * 64 + jj] = W[(size_t)(kc * 32 + kk) * HH + jt0 + jj];
        }
        __syncthreads();
#pragma unroll 8
        for (int kk = 0; kk < 32; kk++) {
            float4 w4 = *(const float4*)&ws[kk * 64 + tn * 4];
            float4 xA = *(const float4*)&xs[kk * 132 + tm * 8];
            float4 xB = *(const float4*)&xs[kk * 132 + tm * 8 + 4];
            float hv[8] = {xA.x, xA.y, xA.z, xA.w, xB.x, xB.y, xB.z, xB.w};
            float wv[4] = {w4.x, w4.y, w4.z, w4.w};
#pragma unroll
            for (int i = 0; i < 8; i++)
#pragma unroll
                for (int j = 0; j < 4; j++)
                    acc[i][j] = fmaf(hv[i], wv[j], acc[i][j]);
        }
        __syncthreads();
    }

#pragma unroll
    for (int i = 0; i < 8; i++) {
        int m = m0 + tm * 8 + i;
        int t = m >> 6, b = m & 63;
        size_t base = (((size_t)t * 3 + gate) * BB + b) * HH + jt0 + tn * 4;
#pragma unroll
        for (int j = 0; j < 4; j++)
            g_Gx[base + j] = acc[i][j] + bias[jt0 + tn * 4 + j];
    }
}

// =====================================================================================
// Phase 2: persistent GRU recurrence. 128 CTAs = 8 groups x 16 CTAs.
// Warp-per-(gate,j-tile-of-8) mapping; lanes span consecutive k -> conflict-free LDS
// (w via XOR float4-slot swizzle, hbuf via 12-float row pad). 8x8 register tiles,
// split-butterfly reduction (lane owns 2 outputs).
// =====================================================================================
__global__ void __launch_bounds__(NT, 1) phase2_gru(
    const float* __restrict__ h0,
    const float* __restrict__ Wz,
    const float* __restrict__ Wr,
    const float* __restrict__ Wh,
    float* __restrict__ out)
{
    extern __shared__ float sm[];
    float* wzs  = sm;                     // [512][32] swizzled
    float* wrs  = wzs + HH * JC;
    float* whs  = wrs + HH * JC;
    float* hbuf = whs + HH * JC;          // [512][HPAD]
    float* z_s  = hbuf + HH * HPAD;       // [8][32]
    float* ho_s = z_s + GB * JC;          // [8][32]
    float* part = ho_s + GB * JC;         // [4][64] stage-2 cross-warp partials

    const int grp  = blockIdx.x >> 4;
    const int rank = blockIdx.x & 15;
    const int b0 = grp * GB;
    const int j0 = rank * JC;
    const int tid  = threadIdx.x;
    const int warp = tid >> 5;
    const int lane = tid & 31;

    // -------- resident recurrent weights (rows DD..DD+511), float4-slot swizzled ----
    for (int idx = tid; idx < HH * JC; idx += NT) {
        int k = idx >> 5, jl = idx & 31;
        int phys = k * JC + ((((jl >> 2) ^ (k & 7))) << 2) + (jl & 3);
        size_t goff = (size_t)(DD + k) * HH + j0 + jl;
        wzs[phys] = Wz[goff];
        wrs[phys] = Wr[goff];
        whs[phys] = Wh[goff];
    }
    __syncthreads();

    const int gate1 = warp >> 2;          // stage1: 0=z warps, 1=r warps
    const int jt    = warp & 3;           // j-tile of 8 cols (both stages)
    const int khalf = warp >> 2;          // stage2: k-half 0/1
    const int bown  = lane >> 2;          // batch element owned post-reduction
    const int jbase = (lane & 3) << 1;    // 2 owned cols within the 8-tile
    const int slotA = (jt * 2) ^ (lane & 7);       // swizzled float4 slots (k-stride 32
    const int slotB = (jt * 2 + 1) ^ (lane & 7);   //  keeps k&7 == lane&7 -> hoisted)

    for (int t = 0; t < TT; t++) {
        // ---------------- fill hbuf with h (transposed, padded rows) ----------------
        const float* hsrc = (t == 0) ? h0 : (const float*)g_h;
#pragma unroll
        for (int q = 0; q < 2; q++) {
            int kk = tid + q * NT;
#pragma unroll
            for (int b = 0; b < GB; b++)
                hbuf[kk * HPAD + b] = __ldcg(&hsrc[(size_t)(b0 + b) * HH + kk]);
        }
        __syncthreads();

        // stash h_old for own columns (read in stage-2 update after hbuf is reused)
        { int b = tid >> 5, jl = tid & 31; ho_s[tid] = hbuf[(j0 + jl) * HPAD + b]; }

        // prefetch Gx (stage 1)
        float gx1[2];
#pragma unroll
        for (int i = 0; i < 2; i++) {
            int jl = jt * 8 + jbase + i;
            gx1[i] = __ldg(&g_Gx[(((size_t)t * 3 + gate1) * BB + b0 + bown) * HH + j0 + jl]);
        }

        // ---------------- stage 1 dot: full K=512 per warp, 8x8 tiles ----------------
        float a[64];
#pragma unroll
        for (int v = 0; v < 64; v++) a[v] = 0.f;
        {
            const float* wg = gate1 ? wrs : wzs;
            const float4* wp = (const float4*)(wg + lane * JC);
            const float4* hp = (const float4*)(hbuf + lane * HPAD);
#pragma unroll
            for (int i = 0; i < 16; i++) {
                float4 w0 = wp[slotA], w1 = wp[slotB];
                float4 hA = hp[0],     hB = hp[1];
                float wv[8] = {w0.x, w0.y, w0.z, w0.w, w1.x, w1.y, w1.z, w1.w};
                float hv[8] = {hA.x, hA.y, hA.z, hA.w, hB.x, hB.y, hB.z, hB.w};
#pragma unroll
                for (int b = 0; b < 8; b++)
#pragma unroll
                    for (int j = 0; j < 8; j++)
                        a[b * 8 + j] = fmaf(hv[b], wv[j], a[b * 8 + j]);
                wp += 32 * JC / 4;      // k += 32
                hp += 32 * HPAD / 4;
            }
        }
        // split-butterfly reduction: lane ends owning v = 2*lane + {0,1}
#pragma unroll
        for (int s = 0; s < 5; s++) {
            const int m = 16 >> s;
            const int half = 32 >> s;
            bool up = (lane & m) != 0;
#pragma unroll
            for (int i = 0; i < half; i++) {
                float send = up ? a[i] : a[i + half];
                float r = __shfl_xor_sync(0xffffffffu, send, m);
                a[i] = (up ? a[i + half] : a[i]) + r;
            }
        }
        // stage-1 epilogue: z -> smem, r*h -> global (L2)
#pragma unroll
        for (int i = 0; i < 2; i++) {
            int jl = jt * 8 + jbase + i;
            float pre = a[i] + gx1[i];
            float sgm = 1.f / (1.f + __expf(-pre));
            if (gate1 == 0) {
                z_s[bown * JC + jl] = sgm;
            } else {
                float rhv = sgm * hbuf[(j0 + jl) * HPAD + bown];
                __stcg(&g_rh[(size_t)(b0 + bown) * HH + j0 + jl], rhv);
            }
        }

        group_barrier(grp);   // g_rh complete group-wide

        // ---------------- stage 2: fill hbuf with r*h ----------------
#pragma unroll
        for (int q = 0; q < 2; q++) {
            int kk = tid + q * NT;
#pragma unroll
            for (int b = 0; b < GB; b++)
                hbuf[kk * HPAD + b] = __ldcg(&g_rh[(size_t)(b0 + b) * HH + kk]);
        }
        __syncthreads();

        float gx2[2];
#pragma unroll
        for (int i = 0; i < 2; i++) {
            int jl = jt * 8 + jbase + i;
            gx2[i] = __ldg(&g_Gx[(((size_t)t * 3 + 2) * BB + b0 + bown) * HH + j0 + jl]);
        }

        // stage-2 dot: half K per warp (k in [khalf*256, +256))
#pragma unroll
        for (int v = 0; v < 64; v++) a[v] = 0.f;
        {
            const int k0 = khalf * 256 + lane;
            const float4* wp = (const float4*)(whs + k0 * JC);
            const float4* hp = (const float4*)(hbuf + k0 * HPAD);
#pragma unroll
            for (int i = 0; i < 8; i++) {
                float4 w0 = wp[slotA], w1 = wp[slotB];
                float4 hA = hp[0],     hB = hp[1];
                float wv[8] = {w0.x, w0.y, w0.z, w0.w, w1.x, w1.y, w1.z, w1.w};
                float hv[8] = {hA.x, hA.y, hA.z, hA.w, hB.x, hB.y, hB.z, hB.w};
#pragma unroll
                for (int b = 0; b < 8; b++)
#pragma unroll
                    for (int j = 0; j < 8; j++)
                        a[b * 8 + j] = fmaf(hv[b], wv[j], a[b * 8 + j]);
                wp += 32 * JC / 4;
                hp += 32 * HPAD / 4;
            }
        }
#pragma unroll
        for (int s = 0; s < 5; s++) {
            const int m = 16 >> s;
            const int half = 32 >> s;
            bool up = (lane & m) != 0;
#pragma unroll
            for (int i = 0; i < half; i++) {
                float send = up ? a[i] : a[i + half];
                float r = __shfl_xor_sync(0xffffffffu, send, m);
                a[i] = (up ? a[i + half] : a[i]) + r;
            }
        }
        // cross-warp combine (2 k-halves) + update epilogue
        if (khalf == 1) {
            part[jt * 64 + lane * 2 + 0] = a[0];
            part[jt * 64 + lane * 2 + 1] = a[1];
        }
        __syncthreads();
        if (khalf == 0) {
#pragma unroll
            for (int i = 0; i < 2; i++) {
                int jl = jt * 8 + jbase + i;
                float sum = a[i] + part[jt * 64 + lane * 2 + i];
                float ht  = tanhf(sum + gx2[i]);
                float z   = z_s[bown * JC + jl];
                float ho  = ho_s[bown * JC + jl];
                float hn  = ho + z * (ht - ho);
                __stcg(&g_h[(size_t)(b0 + bown) * HH + j0 + jl], hn);
                out[((size_t)t * BB + b0 + bown) * HH + j0 + jl] = hn;
            }
        }

        group_barrier(grp);   // g_h complete before next step
    }
}

// =====================================================================================
extern "C" void kernel_launch(void* const* d_in, const int* in_sizes, int n_in,
                              void* d_out, int out_size)
{
    const float* x  = (const float*)d_in[0];
    const float* h0 = (const float*)d_in[1];
    const float* Wz = (const float*)d_in[2];
    const float* bz = (const float*)d_in[3];
    const float* Wr = (const float*)d_in[4];
    const float* br = (const float*)d_in[5];
    const float* Wh = (const float*)d_in[6];
    const float* bh = (const float*)d_in[7];
    float* out = (float*)d_out;

    const int smem_bytes = (3 * HH * JC + HH * HPAD + 2 * GB * JC + 4 * 64) * (int)sizeof(float);
    cudaFuncSetAttribute(phase2_gru, cudaFuncAttributeMaxDynamicSharedMemorySize, smem_bytes);

    dim3 g1((TT * BB) / 128, 24);
    phase1_gemm<<<g1, 256>>>(x, Wz, bz, Wr, br, Wh, bh);

    phase2_gru<<<NGROUPS * GC, NT, smem_bytes>>>(h0, Wz, Wr, Wh, out);
}

// round 5
// speedup vs baseline: 3.5825x; 1.2072x over previous
#include <cuda_runtime.h>
#include <math.h>

#define TT 2048
#define BB 64
#define DD 256
#define HH 512

#define NGROUPS 8
#define GC 16         // CTAs per group
#define GB 8          // batch elems per group
#define JC 32         // output columns owned per CTA
#define NT 256
#define HPAD 12       // hbuf row pad: 12 floats (16B-aligned rows, conflict-free LDS.128)

// ---------------- packed fp32x2 helpers (FFMA2 path: ptxas never auto-fuses) --------
#define FMA_X2(d, a, b, c) \
    asm("fma.rn.f32x2 %0, %1, %2, %3;" : "=l"(d) : "l"(a), "l"(b), "l"(c))
#define ADD_X2(d, a, b) \
    asm("add.rn.f32x2 %0, %1, %2;" : "=l"(d) : "l"(a), "l"(b))
#define DUP_X2(d, s) \
    asm("mov.b64 %0, {%1, %1};" : "=l"(d) : "r"(__float_as_uint(s)))
#define UNPACK_X2(lo, hi, p) \
    asm("mov.b64 {%0, %1}, %2;" : "=r"(lo), "=r"(hi) : "l"(p))

// ---------------- device scratch ----------------
__device__ float g_Gx[(size_t)TT * 3 * BB * HH];
__device__ float g_h[BB * HH];
__device__ float g_rh[BB * HH];
__device__ unsigned g_bcnt[NGROUPS];
__device__ unsigned g_bgen[NGROUPS];

// ---------------- group barrier: acq/rel atomics, no MEMBAR.GPU, replay-safe --------
__device__ __forceinline__ void group_barrier(int grp) {
    __syncthreads();
    if (threadIdx.x == 0) {
        unsigned gen;
        asm volatile("ld.acquire.gpu.global.u32 %0, [%1];"
                     : "=r"(gen) : "l"(&g_bgen[grp]));
        unsigned old;
        asm volatile("atom.acq_rel.gpu.global.add.u32 %0, [%1], %2;"
                     : "=r"(old) : "l"(&g_bcnt[grp]), "r"(1u));
        if (old == GC - 1u) {
            asm volatile("st.relaxed.gpu.global.u32 [%0], %1;"
                         :: "l"(&g_bcnt[grp]), "r"(0u));
            asm volatile("st.release.gpu.global.u32 [%0], %1;"
                         :: "l"(&g_bgen[grp]), "r"(gen + 1u));
        } else {
            unsigned cur;
            do {
                asm volatile("ld.acquire.gpu.global.u32 %0, [%1];"
                             : "=r"(cur) : "l"(&g_bgen[grp]));
            } while (cur == gen);
        }
    }
    __syncthreads();
}

// =====================================================================================
// Phase 1: Gx[t][gate][b][j] = x[t,b,:] @ Wg[0:256,:] + bg   — f32x2 packed GEMM
// =====================================================================================
__global__ void __launch_bounds__(256) phase1_gemm(
    const float* __restrict__ x,
    const float* __restrict__ Wz, const float* __restrict__ bz,
    const float* __restrict__ Wr, const float* __restrict__ br,
    const float* __restrict__ Wh, const float* __restrict__ bh)
{
    __shared__ float xs[32 * 132];   // [k][m] padded rows
    __shared__ float ws[32 * 64];    // [k][n]

    const int gate = blockIdx.y >> 3;
    const int jt0  = (blockIdx.y & 7) * 64;
    const float* W    = (gate == 0) ? Wz : ((gate == 1) ? Wr : Wh);
    const float* bias = (gate == 0) ? bz : ((gate == 1) ? br : bh);
    const int m0  = blockIdx.x * 128;
    const int tid = threadIdx.x;
    const int tn = tid & 15;
    const int tm = tid >> 4;

    unsigned long long pa[4][4];     // packed over row-pairs
#pragma unroll
    for (int i = 0; i < 4; i++)
#pragma unroll
        for (int j = 0; j < 4; j++) pa[i][j] = 0ull;

    for (int kc = 0; kc < 8; kc++) {
#pragma unroll
        for (int i = 0; i < 16; i++) {
            int idx = tid + i * 256;
            int row = idx >> 5, kk = idx & 31;
            xs[kk * 132 + row] = x[(size_t)(m0 + row) * DD + kc * 32 + kk];
        }
#pragma unroll
        for (int i = 0; i < 8; i++) {
            int idx = tid + i * 256;
            int kk = idx >> 6, jj = idx & 63;
            ws[kk * 64 + jj] = W[(size_t)(kc * 32 + kk) * HH + jt0 + jj];
        }
        __syncthreads();
#pragma unroll 8
        for (int kk = 0; kk < 32; kk++) {
            float4 w4 = *(const float4*)&ws[kk * 64 + tn * 4];
            ulonglong2 xL = *(const ulonglong2*)&xs[kk * 132 + tm * 8];
            ulonglong2 xH = *(const ulonglong2*)&xs[kk * 132 + tm * 8 + 4];
            unsigned long long hp[4] = {xL.x, xL.y, xH.x, xH.y};
            unsigned long long wd[4];
            DUP_X2(wd[0], w4.x); DUP_X2(wd[1], w4.y);
            DUP_X2(wd[2], w4.z); DUP_X2(wd[3], w4.w);
#pragma unroll
            for (int i = 0; i < 4; i++)
#pragma unroll
                for (int j = 0; j < 4; j++)
                    FMA_X2(pa[i][j], hp[i], wd[j], pa[i][j]);
        }
        __syncthreads();
    }

#pragma unroll
    for (int i = 0; i < 4; i++) {
#pragma unroll
        for (int j = 0; j < 4; j++) {
            unsigned lo, hi;
            UNPACK_X2(lo, hi, pa[i][j]);
            float bj = bias[jt0 + tn * 4 + j];
            int mA = m0 + tm * 8 + 2 * i;
            int tA = mA >> 6, bA = mA & 63;
            g_Gx[(((size_t)tA * 3 + gate) * BB + bA) * HH + jt0 + tn * 4 + j] =
                __uint_as_float(lo) + bj;
            int mB = mA + 1;
            int tB = mB >> 6, bB = mB & 63;
            g_Gx[(((size_t)tB * 3 + gate) * BB + bB) * HH + jt0 + tn * 4 + j] =
                __uint_as_float(hi) + bj;
        }
    }
}

// =====================================================================================
// Phase 2: persistent GRU, f32x2 packed dots.
// 128 CTAs = 8 groups x 16. Warp w: jt = w&3 (8 cols); stage1 gate = w>>2 over full K;
// stage2 khalf = w>>2 over K/2. Lanes = consecutive k; conflict-free LDS via XOR
// float4-slot swizzle (W) + 12-float row pad (hbuf). Packed split-butterfly over 32
// values (half = m = 16>>s): lane ends owning a2[0] = value v = lane
// => (b-pair = lane>>3, col = jt*8 + (lane&7)).
// =====================================================================================
__global__ void __launch_bounds__(NT, 1) phase2_gru(
    const float* __restrict__ h0,
    const float* __restrict__ Wz,
    const float* __restrict__ Wr,
    const float* __restrict__ Wh,
    float* __restrict__ out)
{
    extern __shared__ float sm[];
    float* wzs  = sm;                     // [512][32] swizzled
    float* wrs  = wzs + HH * JC;
    float* whs  = wrs + HH * JC;
    float* hbuf = whs + HH * JC;          // [512][HPAD]
    float* z_s  = hbuf + HH * HPAD;       // [8][32]
    float* ho_s = z_s + GB * JC;          // [8][32]
    unsigned long long* partU = (unsigned long long*)(ho_s + GB * JC);  // [4][32] packed

    const int grp  = blockIdx.x >> 4;
    const int rank = blockIdx.x & 15;
    const int b0 = grp * GB;
    const int j0 = rank * JC;
    const int tid  = threadIdx.x;
    const int warp = tid >> 5;
    const int lane = tid & 31;

    // resident recurrent weights (rows DD..DD+511), float4-slot XOR swizzle
    for (int idx = tid; idx < HH * JC; idx += NT) {
        int k = idx >> 5, jl = idx & 31;
        int phys = k * JC + ((((jl >> 2) ^ (k & 7))) << 2) + (jl & 3);
        size_t goff = (size_t)(DD + k) * HH + j0 + jl;
        wzs[phys] = Wz[goff];
        wrs[phys] = Wr[goff];
        whs[phys] = Wh[goff];
    }
    __syncthreads();

    const int gate1 = warp >> 2;          // stage1: 0=z, 1=r
    const int jt    = warp & 3;           // 8-col tile (both stages)
    const int khalf = warp >> 2;          // stage2 k-half
    const int slotA = (jt * 2) ^ (lane & 7);
    const int slotB = (jt * 2 + 1) ^ (lane & 7);
    const int bp    = lane >> 3;          // owned b-pair after reduction
    const int jl_o  = jt * 8 + (lane & 7);// owned column

    for (int t = 0; t < TT; t++) {
        // ---- prefetch Gx for both stages (DRAM latency hides under dot1) ----
        float gx1lo, gx1hi, gx2lo, gx2hi;
        {
            size_t r1 = (((size_t)t * 3 + gate1) * BB + b0 + 2 * bp) * HH + j0 + jl_o;
            gx1lo = __ldg(&g_Gx[r1]);
            gx1hi = __ldg(&g_Gx[r1 + HH]);
            size_t r2 = (((size_t)t * 3 + 2) * BB + b0 + 2 * bp) * HH + j0 + jl_o;
            gx2lo = __ldg(&g_Gx[r2]);
            gx2hi = __ldg(&g_Gx[r2 + HH]);
        }

        // ---- fill hbuf with h (k-major, padded rows) ----
        const float* hsrc = (t == 0) ? h0 : (const float*)g_h;
#pragma unroll
        for (int q = 0; q < 2; q++) {
            int kk = tid + q * NT;
#pragma unroll
            for (int b = 0; b < GB; b++)
                hbuf[kk * HPAD + b] = __ldcg(&hsrc[(size_t)(b0 + b) * HH + kk]);
        }
        __syncthreads();

        // stash h_old for own columns
        { int b = tid >> 5, jl = tid & 31; ho_s[tid] = hbuf[(j0 + jl) * HPAD + b]; }

        // ================= stage 1 dot (full K=512), packed =================
        unsigned long long a2[32];
#pragma unroll
        for (int v = 0; v < 32; v++) a2[v] = 0ull;
        {
            const float4* wp = (const float4*)((gate1 ? wrs : wzs) + lane * JC);
            const char*   hp = (const char*)(hbuf + lane * HPAD);
#pragma unroll
            for (int i = 0; i < 16; i++) {
                float4 w0 = wp[slotA], w1 = wp[slotB];
                ulonglong2 hL = *(const ulonglong2*)hp;
                ulonglong2 hH = *(const ulonglong2*)(hp + 16);
                unsigned long long hb[4] = {hL.x, hL.y, hH.x, hH.y};
                unsigned long long wd[8];
                DUP_X2(wd[0], w0.x); DUP_X2(wd[1], w0.y);
                DUP_X2(wd[2], w0.z); DUP_X2(wd[3], w0.w);
                DUP_X2(wd[4], w1.x); DUP_X2(wd[5], w1.y);
                DUP_X2(wd[6], w1.z); DUP_X2(wd[7], w1.w);
#pragma unroll
                for (int p = 0; p < 4; p++)
#pragma unroll
                    for (int j = 0; j < 8; j++)
                        FMA_X2(a2[p * 8 + j], hb[p], wd[j], a2[p * 8 + j]);
                wp += 32 * JC / 4;
                hp += 32 * HPAD * 4;
            }
        }
        // packed split-butterfly over 32 values: lane ends owning v = lane
#pragma unroll
        for (int s = 0; s < 5; s++) {
            const int m = 16 >> s;
            const int half = 16 >> s;
            bool up = (lane & m) != 0;
#pragma unroll
            for (int i = 0; i < half; i++) {
                unsigned long long send = up ? a2[i] : a2[i + half];
                unsigned long long r = __shfl_xor_sync(0xffffffffu, send, m);
                unsigned long long keep = up ? a2[i + half] : a2[i];
                ADD_X2(a2[i], keep, r);
            }
        }
        {
            unsigned lo, hi;
            UNPACK_X2(lo, hi, a2[0]);
            float pre0 = __uint_as_float(lo) + gx1lo;
            float pre1 = __uint_as_float(hi) + gx1hi;
            float s0 = 1.f / (1.f + __expf(-pre0));
            float s1 = 1.f / (1.f + __expf(-pre1));
            int bA = 2 * bp, bB = 2 * bp + 1;
            if (gate1 == 0) {
                z_s[bA * JC + jl_o] = s0;
                z_s[bB * JC + jl_o] = s1;
            } else {
                float rh0 = s0 * hbuf[(j0 + jl_o) * HPAD + bA];
                float rh1 = s1 * hbuf[(j0 + jl_o) * HPAD + bB];
                __stcg(&g_rh[(size_t)(b0 + bA) * HH + j0 + jl_o], rh0);
                __stcg(&g_rh[(size_t)(b0 + bB) * HH + j0 + jl_o], rh1);
            }
        }

        group_barrier(grp);   // g_rh complete group-wide

        // ================= stage 2: fill hbuf with r*h =================
#pragma unroll
        for (int q = 0; q < 2; q++) {
            int kk = tid + q * NT;
#pragma unroll
            for (int b = 0; b < GB; b++)
                hbuf[kk * HPAD + b] = __ldcg(&g_rh[(size_t)(b0 + b) * HH + kk]);
        }
        __syncthreads();

        // stage-2 dot (K/2 per warp), packed
#pragma unroll
        for (int v = 0; v < 32; v++) a2[v] = 0ull;
        {
            const int k0 = khalf * 256 + lane;
            const float4* wp = (const float4*)(whs + k0 * JC);
            const char*   hp = (const char*)(hbuf + k0 * HPAD);
#pragma unroll
            for (int i = 0; i < 8; i++) {
                float4 w0 = wp[slotA], w1 = wp[slotB];
                ulonglong2 hL = *(const ulonglong2*)hp;
                ulonglong2 hH = *(const ulonglong2*)(hp + 16);
                unsigned long long hb[4] = {hL.x, hL.y, hH.x, hH.y};
                unsigned long long wd[8];
                DUP_X2(wd[0], w0.x); DUP_X2(wd[1], w0.y);
                DUP_X2(wd[2], w0.z); DUP_X2(wd[3], w0.w);
                DUP_X2(wd[4], w1.x); DUP_X2(wd[5], w1.y);
                DUP_X2(wd[6], w1.z); DUP_X2(wd[7], w1.w);
#pragma unroll
                for (int p = 0; p < 4; p++)
#pragma unroll
                    for (int j = 0; j < 8; j++)
                        FMA_X2(a2[p * 8 + j], hb[p], wd[j], a2[p * 8 + j]);
                wp += 32 * JC / 4;
                hp += 32 * HPAD * 4;
            }
        }
#pragma unroll
        for (int s = 0; s < 5; s++) {
            const int m = 16 >> s;
            const int half = 16 >> s;
            bool up = (lane & m) != 0;
#pragma unroll
            for (int i = 0; i < half; i++) {
                unsigned long long send = up ? a2[i] : a2[i + half];
                unsigned long long r = __shfl_xor_sync(0xffffffffu, send, m);
                unsigned long long keep = up ? a2[i + half] : a2[i];
                ADD_X2(a2[i], keep, r);
            }
        }
        // cross-warp k-half combine + update epilogue
        if (khalf == 1) partU[jt * 32 + lane] = a2[0];
        __syncthreads();
        if (khalf == 0) {
            unsigned long long tot;
            ADD_X2(tot, a2[0], partU[jt * 32 + lane]);
            unsigned lo, hi;
            UNPACK_X2(lo, hi, tot);
            int bA = 2 * bp, bB = 2 * bp + 1;
            float ht0 = tanhf(__uint_as_float(lo) + gx2lo);
            float ht1 = tanhf(__uint_as_float(hi) + gx2hi);
            float z0 = z_s[bA * JC + jl_o], z1 = z_s[bB * JC + jl_o];
            float h0v = ho_s[bA * JC + jl_o], h1v = ho_s[bB * JC + jl_o];
            float hn0 = h0v + z0 * (ht0 - h0v);
            float hn1 = h1v + z1 * (ht1 - h1v);
            __stcg(&g_h[(size_t)(b0 + bA) * HH + j0 + jl_o], hn0);
            __stcg(&g_h[(size_t)(b0 + bB) * HH + j0 + jl_o], hn1);
            out[((size_t)t * BB + b0 + bA) * HH + j0 + jl_o] = hn0;
            out[((size_t)t * BB + b0 + bB) * HH + j0 + jl_o] = hn1;
        }

        group_barrier(grp);   // g_h complete before next step
    }
}

// =====================================================================================
extern "C" void kernel_launch(void* const* d_in, const int* in_sizes, int n_in,
                              void* d_out, int out_size)
{
    const float* x  = (const float*)d_in[0];
    const float* h0 = (const float*)d_in[1];
    const float* Wz = (const float*)d_in[2];
    const float* bz = (const float*)d_in[3];
    const float* Wr = (const float*)d_in[4];
    const float* br = (const float*)d_in[5];
    const float* Wh = (const float*)d_in[6];
    const float* bh = (const float*)d_in[7];
    float* out = (float*)d_out;

    const int smem_bytes = (3 * HH * JC + HH * HPAD + 2 * GB * JC) * (int)sizeof(float)
                         + 4 * 32 * (int)sizeof(unsigned long long);
    cudaFuncSetAttribute(phase2_gru, cudaFuncAttributeMaxDynamicSharedMemorySize, smem_bytes);

    dim3 g1((TT * BB) / 128, 24);
    phase1_gemm<<<g1, 256>>>(x, Wz, bz, Wr, br, Wh, bh);

    phase2_gru<<<NGROUPS * GC, NT, smem_bytes>>>(h0, Wz, Wr, Wh, out);
}